// round 16
// baseline (speedup 1.0000x reference)
#include <cuda_runtime.h>
#include <cuda_bf16.h>
#include <cuda_fp16.h>
#include <cstdint>
#include <math.h>

#define SQ   2048
#define DM   4096
#define PR   2048
#define NH   32
#define DH   128
#define RP   64
#define NKV  6144           // knope(2048) | v(4096)
#define NC1  4160           // cq(2048) | ckv(2048) | krope(64)

#define LOG2E  1.4426950408889634f

// ===================== small helpers ========================================
static __device__ __forceinline__ uint32_t smem_u32(const void* p) {
    uint32_t a;
    asm("{ .reg .u64 t; cvta.to.shared.u64 t, %1; cvt.u32.u64 %0, t; }"
        : "=r"(a) : "l"(p));
    return a;
}

// pack two floats -> fp16x2 (lo half = a, hi half = b)
static __device__ __forceinline__ uint32_t cvt_f16x2(float a, float b) {
    uint32_t r;
    asm("cvt.rn.f16x2.f32 %0, %1, %2;" : "=r"(r) : "f"(b), "f"(a));
    return r;
}

#define LDSM4(r, addr) \
    asm volatile("ldmatrix.sync.aligned.m8n8.x4.shared.b16 {%0,%1,%2,%3}, [%4];" \
        : "=r"((r)[0]), "=r"((r)[1]), "=r"((r)[2]), "=r"((r)[3]) : "r"(addr))

#define LDSM4_T(r, addr) \
    asm volatile("ldmatrix.sync.aligned.m8n8.x4.trans.shared.b16 {%0,%1,%2,%3}, [%4];" \
        : "=r"((r)[0]), "=r"((r)[1]), "=r"((r)[2]), "=r"((r)[3]) : "r"(addr))

#define MMA16(d, a, b0v, b1v) \
    asm volatile("mma.sync.aligned.m16n8k16.row.col.f32.f16.f16.f32 " \
        "{%0,%1,%2,%3}, {%4,%5,%6,%7}, {%8,%9}, {%0,%1,%2,%3};" \
        : "+f"((d)[0]), "+f"((d)[1]), "+f"((d)[2]), "+f"((d)[3]) \
        : "r"((a)[0]), "r"((a)[1]), "r"((a)[2]), "r"((a)[3]), "r"(b0v), "r"(b1v))

#define CP_ASYNC16(sp, gp) \
    asm volatile("cp.async.cg.shared.global [%0], [%1], 16;" :: "r"(sp), "l"(gp))
#define CP_COMMIT() asm volatile("cp.async.commit_group;" ::: "memory")
#define CP_WAIT3()  asm volatile("cp.async.wait_group 3;" ::: "memory")
#define CP_WAIT1()  asm volatile("cp.async.wait_group 1;" ::: "memory")

// ===================== scratch (device globals) =============================
__device__ __half g_xf  [(size_t)SQ * DM];
__device__ __half g_cqkv[(size_t)SQ * NC1];      // cq | ckv | krope
__device__ __half g_qf  [(size_t)SQ * DM];       // q (rope applied inside FA)
__device__ __half g_kvf [(size_t)SQ * NKV];      // knope | v
__device__ __half g_aof [(size_t)SQ * DM];

// fp16 weights ([N,K] K-major)
__device__ __half g_wdqkv[(size_t)NC1 * DM];     // [W_DQ; W_DKV; W_K_rope]
__device__ __half g_wuq  [(size_t)DM * PR];
__device__ __half g_wukuv[(size_t)NKV * PR];     // [W_UK; W_UV]
__device__ __half g_wo   [(size_t)DM * DM];

// ===================== single-fp16 HMMA GEMM ================================
// C = alpha * A @ B^T (+bias).  A: fp16 [M,K] row-major, B: fp16 [N,K] K-major.
// CTA tile 128x128, BK=32, 8 warps (2x4), warp tile 64x32, 4-stage cp.async.
#define STAGE_BYTES 20480
#define GEMM_SMEM   (4 * STAGE_BYTES)  // 81920

__global__ void __launch_bounds__(256, 2)
gemm_f16(const __half* __restrict__ Af, const __half* __restrict__ Bh,
         float* __restrict__ Cf, __half* __restrict__ Ch,
         int M, int N, int K, int lda, int ldb, int ldc,
         float alpha, const float* __restrict__ bias)
{
    extern __shared__ char smem[];
    const uint32_t sbase = smem_u32(smem);
    const int tid  = threadIdx.x;
    const int lane = tid & 31;
    const int w    = tid >> 5;
    const int wm   = w & 1;
    const int wn   = w >> 1;

    const int m0 = blockIdx.y * 128;
    const int n0 = blockIdx.x * 128;
    const int nk = K >> 5;

    const int lr   = tid >> 2;
    const int lcol = tid & 3;

    auto load_stage = [&](int kt, int slot) {
        const int k0 = kt << 5;
        const uint32_t sb = sbase + slot * STAGE_BYTES;
#pragma unroll
        for (int i = 0; i < 2; ++i) {
            const int r = lr + i * 64;
            const __half* gp = Af + (long long)(m0 + r) * lda + k0 + lcol * 8;
            CP_ASYNC16(sb + r * 80 + lcol * 16, gp);
        }
#pragma unroll
        for (int i = 0; i < 2; ++i) {
            const int r = lr + i * 64;
            int rn = n0 + r; if (rn >= N) rn = N - 1;
            const __half* gp = Bh + (long long)rn * ldb + k0 + lcol * 8;
            CP_ASYNC16(sb + 10240 + r * 80 + lcol * 16, gp);
        }
        CP_COMMIT();
    };

    const uint32_t aOff = (uint32_t)((wm * 64 + (lane & 15)) * 80 + ((lane >> 4) & 1) * 16);
    const uint32_t bOff = (uint32_t)((wn * 32 + ((lane >> 4) & 1) * 8 + (lane & 7)) * 80
                                     + ((lane >> 3) & 1) * 16);

    float acc[4][4][4];
#pragma unroll
    for (int a = 0; a < 4; a++)
#pragma unroll
        for (int b = 0; b < 4; b++)
#pragma unroll
            for (int c = 0; c < 4; c++) acc[a][b][c] = 0.0f;

    load_stage(0, 0);
    if (nk > 1) load_stage(1, 1); else CP_COMMIT();
    if (nk > 2) load_stage(2, 2); else CP_COMMIT();

    for (int kt = 0; kt < nk; ++kt) {
        if (kt + 3 < nk) load_stage(kt + 3, (kt + 3) & 3);
        else CP_COMMIT();
        CP_WAIT3();
        __syncthreads();

        const uint32_t sb = sbase + (kt & 3) * STAGE_BYTES;
#pragma unroll
        for (int kk = 0; kk < 2; ++kk) {
            uint32_t af[4][4], bh[2][4];
#pragma unroll
            for (int mt = 0; mt < 4; ++mt)
                LDSM4(af[mt], sb + aOff + mt * 1280 + kk * 32);
#pragma unroll
            for (int bt = 0; bt < 2; ++bt)
                LDSM4(bh[bt], sb + 10240 + bOff + bt * 1280 + kk * 32);
#pragma unroll
            for (int mt = 0; mt < 4; ++mt)
#pragma unroll
                for (int nt = 0; nt < 4; ++nt) {
                    const int bt = nt >> 1, s2 = (nt & 1) * 2;
                    MMA16(acc[mt][nt], af[mt], bh[bt][s2], bh[bt][s2 + 1]);
                }
        }
        __syncthreads();
    }

    const int er = lane >> 2;
    const int ec = (lane & 3) << 1;
#pragma unroll
    for (int mt = 0; mt < 4; ++mt) {
#pragma unroll
        for (int nt = 0; nt < 4; ++nt) {
            const int gr = m0 + wm * 64 + mt * 16 + er;
            const int gc = n0 + wn * 32 + nt * 8 + ec;
            if (gc >= N) continue;
            float v0 = acc[mt][nt][0] * alpha;
            float v1 = acc[mt][nt][1] * alpha;
            float v2 = acc[mt][nt][2] * alpha;
            float v3 = acc[mt][nt][3] * alpha;
            if (bias) {
                const float b0 = bias[gc], b1 = bias[gc + 1];
                v0 += b0; v1 += b1; v2 += b0; v3 += b1;
            }
            const long long o0 = (long long)gr * ldc + gc;
            const long long o1 = (long long)(gr + 8) * ldc + gc;
            if (Cf) {
                *(float2*)&Cf[o0] = make_float2(v0, v1);
                *(float2*)&Cf[o1] = make_float2(v2, v3);
            }
            if (Ch) {
                *(uint32_t*)&Ch[o0] = cvt_f16x2(v0, v1);
                *(uint32_t*)&Ch[o1] = cvt_f16x2(v2, v3);
            }
        }
    }
}

// ===================== fused flash attention =================================
// 64-row Q tiles, 128 threads (4 warps), 2 CTAs/SM.  Online softmax.
// Q: [s][h*DH+d] (un-roped; rope applied to the smem tile once).
// K assembled on the fly: knope from kvf, krope from cqkv (pre-roped).
// V read directly from kvf rows (keys x d); PV uses ldmatrix.trans.
#define FA_QPITCH 272
#define FA_KPITCH 272
#define FA_VPITCH 272
#define FA_Q      0
#define FA_KBUF   17408                 // Q: 64*272
#define FA_VBUF   (FA_KBUF + 2 * 17408) // K: 2 bufs x 64*272
#define FA_SMEM   (FA_VBUF + 2 * 17408) // + V: 2 bufs x 64*272 = 87040

__global__ void __launch_bounds__(128, 2)
fa_kernel(const __half* __restrict__ Qf,
          const __half* __restrict__ kvf, const __half* __restrict__ cqkv,
          __half* __restrict__ O, const int* __restrict__ past)
{
    extern __shared__ char smem[];
    const uint32_t sb = smem_u32(smem);
    const int tid  = threadIdx.x;
    const int lane = tid & 31;
    const int w    = tid >> 5;          // 0..3
    const int h    = blockIdx.y;
    const int m0   = blockIdx.x * 64;

    // Q tile: 64 rows x 256 B
    {
        const __half* qg = Qf + (size_t)m0 * DM + h * DH;
#pragma unroll
        for (int i = 0; i < 8; ++i) {
            const int id = tid + i * 128;
            const int r = id >> 4, c = id & 15;
            CP_ASYNC16(sb + FA_Q + r * FA_QPITCH + c * 16, qg + (size_t)r * DM + c * 8);
        }
    }
    auto loadKV = [&](int c, int buf) {
        const int k0 = c << 6;
        const uint32_t kb = sb + FA_KBUF + buf * 17408;
#pragma unroll
        for (int i = 0; i < 8; ++i) {
            const int id = tid + i * 128;
            const int r = id >> 4, cc = id & 15;
            const __half* gp;
            if (cc < 8)
                gp = kvf + (size_t)(k0 + r) * NKV + h * 64 + cc * 8;
            else
                gp = cqkv + (size_t)(k0 + r) * NC1 + 4096 + (cc - 8) * 8;
            CP_ASYNC16(kb + r * FA_KPITCH + cc * 16, gp);
        }
        const uint32_t vb = sb + FA_VBUF + buf * 17408;
#pragma unroll
        for (int i = 0; i < 8; ++i) {
            const int id = tid + i * 128;
            const int r = id >> 4, cc = id & 15;
            CP_ASYNC16(vb + r * FA_VPITCH + cc * 16,
                       kvf + (size_t)(k0 + r) * NKV + PR + h * DH + cc * 8);
        }
    };

    loadKV(0, 0);
    CP_COMMIT();

    const int past0 = past[0];

    const uint32_t qOff = sb + FA_Q + (w * 16 + (lane & 15)) * FA_QPITCH
                          + ((lane >> 4) & 1) * 16;
    const uint32_t kOff = (uint32_t)((((lane >> 4) & 1) * 8 + (lane & 7)) * FA_KPITCH
                          + ((lane >> 3) & 1) * 16);
    const uint32_t vOff = (uint32_t)(((lane & 7) + ((lane >> 3) & 1) * 8) * FA_VPITCH
                          + ((lane >> 4) & 1) * 16);

    float acc_o[16][4];
#pragma unroll
    for (int i = 0; i < 16; ++i)
#pragma unroll
        for (int j = 0; j < 4; ++j) acc_o[i][j] = 0.0f;

    float mr0 = -1e30f, mr1 = -1e30f, l0 = 0.0f, l1 = 0.0f;
    const float sc_al = 0.08838834764831845f * LOG2E;

    const int NC = SQ / 64;
    for (int c = 0; c < NC; ++c) {
        if (c + 1 < NC) loadKV(c + 1, (c + 1) & 1);
        CP_COMMIT();
        CP_WAIT1();
        __syncthreads();

        if (c == 0) {
            // one-time in-smem rope of the Q tile (cols 64..127 of each row)
#pragma unroll
            for (int j = 0; j < 16; ++j) {
                const int idx = tid + j * 128;        // 0..2047
                const int row = idx >> 5;
                const int i   = idx & 31;
                __half* base = (__half*)(smem + FA_Q + row * FA_QPITCH) + 64;
                const float fr = __expf(-(2.0f * (float)i / 128.0f) * 9.210340371976184f);
                const float ang = (float)(past0 + m0 + row) * fr;
                const float cc = cosf(ang), sn = sinf(ang);
                const float a = __half2float(base[i]);
                const float b = __half2float(base[i + 32]);
                base[i]      = __float2half_rn(a * cc - b * sn);
                base[i + 32] = __float2half_rn(b * cc + a * sn);
            }
            __syncthreads();
        }

        const uint32_t kb = sb + FA_KBUF + (c & 1) * 17408;
        const uint32_t vb = sb + FA_VBUF + (c & 1) * 17408;

        float s[8][4];
#pragma unroll
        for (int i = 0; i < 8; ++i)
#pragma unroll
            for (int j = 0; j < 4; ++j) s[i][j] = 0.0f;

#pragma unroll
        for (int kk = 0; kk < 8; ++kk) {
            uint32_t aq[4];
            LDSM4(aq, qOff + kk * 32);
#pragma unroll
            for (int ntp = 0; ntp < 4; ++ntp) {
                uint32_t kh4[4];
                LDSM4(kh4, kb + kOff + ntp * (16 * FA_KPITCH) + kk * 32);
                MMA16(s[2 * ntp],     aq, kh4[0], kh4[1]);
                MMA16(s[2 * ntp + 1], aq, kh4[2], kh4[3]);
            }
        }
#pragma unroll
        for (int nt = 0; nt < 8; ++nt)
#pragma unroll
            for (int j = 0; j < 4; ++j)
                s[nt][j] *= sc_al;

        float mx0 = -1e30f, mx1 = -1e30f;
#pragma unroll
        for (int nt = 0; nt < 8; ++nt) {
            mx0 = fmaxf(mx0, fmaxf(s[nt][0], s[nt][1]));
            mx1 = fmaxf(mx1, fmaxf(s[nt][2], s[nt][3]));
        }
        mx0 = fmaxf(mx0, __shfl_xor_sync(0xffffffffu, mx0, 1));
        mx0 = fmaxf(mx0, __shfl_xor_sync(0xffffffffu, mx0, 2));
        mx1 = fmaxf(mx1, __shfl_xor_sync(0xffffffffu, mx1, 1));
        mx1 = fmaxf(mx1, __shfl_xor_sync(0xffffffffu, mx1, 2));

        const float mn0 = fmaxf(mr0, mx0);
        const float mn1 = fmaxf(mr1, mx1);
        const float sc0 = exp2f(mr0 - mn0);
        const float sc1 = exp2f(mr1 - mn1);

        float rs0 = 0.0f, rs1 = 0.0f;
#pragma unroll
        for (int nt = 0; nt < 8; ++nt) {
            s[nt][0] = exp2f(s[nt][0] - mn0);
            s[nt][1] = exp2f(s[nt][1] - mn0);
            s[nt][2] = exp2f(s[nt][2] - mn1);
            s[nt][3] = exp2f(s[nt][3] - mn1);
            rs0 += s[nt][0] + s[nt][1];
            rs1 += s[nt][2] + s[nt][3];
        }
        rs0 += __shfl_xor_sync(0xffffffffu, rs0, 1);
        rs0 += __shfl_xor_sync(0xffffffffu, rs0, 2);
        rs1 += __shfl_xor_sync(0xffffffffu, rs1, 1);
        rs1 += __shfl_xor_sync(0xffffffffu, rs1, 2);

        l0 = l0 * sc0 + rs0;
        l1 = l1 * sc1 + rs1;
        mr0 = mn0;  mr1 = mn1;

#pragma unroll
        for (int nt = 0; nt < 16; ++nt) {
            acc_o[nt][0] *= sc0;  acc_o[nt][1] *= sc0;
            acc_o[nt][2] *= sc1;  acc_o[nt][3] *= sc1;
        }

#pragma unroll
        for (int kg = 0; kg < 4; ++kg) {
            uint32_t A[4];
            A[0] = cvt_f16x2(s[2 * kg][0],     s[2 * kg][1]);
            A[1] = cvt_f16x2(s[2 * kg][2],     s[2 * kg][3]);
            A[2] = cvt_f16x2(s[2 * kg + 1][0], s[2 * kg + 1][1]);
            A[3] = cvt_f16x2(s[2 * kg + 1][2], s[2 * kg + 1][3]);
#pragma unroll
            for (int dp = 0; dp < 8; ++dp) {
                uint32_t vh4[4];
                LDSM4_T(vh4, vb + vOff + kg * (16 * FA_VPITCH) + dp * 32);
                MMA16(acc_o[2 * dp],     A, vh4[0], vh4[1]);
                MMA16(acc_o[2 * dp + 1], A, vh4[2], vh4[3]);
            }
        }
        __syncthreads();
    }

    const float i0 = 1.0f / l0;
    const float i1 = 1.0f / l1;
    const int er = lane >> 2;
    const int ec = (lane & 3) << 1;
    const int gr0 = m0 + w * 16 + er;
    __half* ob = O + (size_t)gr0 * DM + h * DH + ec;
#pragma unroll
    for (int nt = 0; nt < 16; ++nt) {
        *(uint32_t*)(ob + nt * 8) =
            cvt_f16x2(acc_o[nt][0] * i0, acc_o[nt][1] * i0);
        *(uint32_t*)(ob + (size_t)8 * DM + nt * 8) =
            cvt_f16x2(acc_o[nt][2] * i1, acc_o[nt][3] * i1);
    }
}

// ===================== fp32 -> fp16 convert ==================================
__global__ void conv_f16(const float4* __restrict__ in, uint2* __restrict__ o, int n4)
{
    const int i = blockIdx.x * blockDim.x + threadIdx.x;
    if (i >= n4) return;
    const float4 f = in[i];
    o[i] = make_uint2(cvt_f16x2(f.x, f.y), cvt_f16x2(f.z, f.w));
}

// ===================== transpose fp32 [K,N] -> fp16 [N,K] ====================
__global__ void transpose_f16w(const float* __restrict__ in,
                               __half* __restrict__ o, int ldin, int ldout)
{
    __shared__ float t[32][33];
    const int c0 = blockIdx.x * 32, r0 = blockIdx.y * 32;
    const int tx = threadIdx.x, ty = threadIdx.y;
#pragma unroll
    for (int j = 0; j < 32; j += 8)
        t[ty + j][tx] = in[(long long)(r0 + ty + j) * ldin + c0 + tx];
    __syncthreads();
#pragma unroll
    for (int j = 0; j < 32; j += 8)
        o[(long long)(c0 + ty + j) * ldout + r0 + tx] = __float2half_rn(t[tx][ty + j]);
}

// ===================== RoPE: krope columns inside cqkv (in-place fp16) =======
__global__ void rope_k16(__half* __restrict__ cqkv, const int* __restrict__ past)
{
    const int idx = blockIdx.x * blockDim.x + threadIdx.x;
    if (idx >= SQ * 32) return;
    const int s = idx / 32;
    const int i = idx % 32;
    __half* base = cqkv + (size_t)s * NC1 + 4096;

    const float fr = __expf(-(2.0f * (float)i / 128.0f) * 9.210340371976184f);
    const float ang = (float)(past[0] + s) * fr;
    const float c = cosf(ang), sn = sinf(ang);
    const float a = __half2float(base[i]);
    const float b = __half2float(base[i + 32]);
    base[i]      = __float2half_rn(a * c - b * sn);
    base[i + 32] = __float2half_rn(b * c + a * sn);
}

// ===================== launch ================================================
extern "C" void kernel_launch(void* const* d_in, const int* in_sizes, int n_in,
                              void* d_out, int out_size)
{
    const float* x        = (const float*)d_in[0];
    const float* W_DQ     = (const float*)d_in[1];
    const float* W_UQ     = (const float*)d_in[2];
    const float* W_DKV    = (const float*)d_in[3];
    const float* W_UK     = (const float*)d_in[4];
    const float* W_UV     = (const float*)d_in[5];
    const float* W_K_rope = (const float*)d_in[6];
    const float* W_O      = (const float*)d_in[7];
    const float* b_O      = (const float*)d_in[8];
    const int*   past     = (const int*)d_in[9];
    float* out = (float*)d_out;

    __half *xf, *cqkv, *qf, *kvf, *aof, *wdqkv, *wuq, *wukuv, *wo;
    cudaGetSymbolAddress((void**)&xf,    g_xf);
    cudaGetSymbolAddress((void**)&cqkv,  g_cqkv);
    cudaGetSymbolAddress((void**)&qf,    g_qf);
    cudaGetSymbolAddress((void**)&kvf,   g_kvf);
    cudaGetSymbolAddress((void**)&aof,   g_aof);
    cudaGetSymbolAddress((void**)&wdqkv, g_wdqkv);
    cudaGetSymbolAddress((void**)&wuq,   g_wuq);
    cudaGetSymbolAddress((void**)&wukuv, g_wukuv);
    cudaGetSymbolAddress((void**)&wo,    g_wo);

    cudaFuncSetAttribute(gemm_f16,  cudaFuncAttributeMaxDynamicSharedMemorySize, GEMM_SMEM);
    cudaFuncSetAttribute(fa_kernel, cudaFuncAttributeMaxDynamicSharedMemorySize, FA_SMEM);

    const dim3 blk(256);
    const dim3 tb(32, 8);

    // setup
    conv_f16<<<(SQ * DM / 4 + 255) / 256, blk>>>(
        (const float4*)x, (uint2*)xf, SQ * DM / 4);
    transpose_f16w<<<dim3(PR / 32, DM / 32), tb>>>(W_DQ,     wdqkv,                       PR, DM);
    transpose_f16w<<<dim3(PR / 32, DM / 32), tb>>>(W_DKV,    wdqkv + (size_t)PR * DM,     PR, DM);
    transpose_f16w<<<dim3(RP / 32, DM / 32), tb>>>(W_K_rope, wdqkv + (size_t)4096 * DM,   RP, DM);
    transpose_f16w<<<dim3(PR / 32, PR / 32), tb>>>(W_UK,     wukuv,                       PR, PR);

    // cq|ckv|krope = x @ [W_DQ; W_DKV; W_K_rope]  (N=4160, fp16 out)
    gemm_f16<<<dim3((NC1 + 127) / 128, SQ / 128), blk, GEMM_SMEM>>>(
        xf, wdqkv, nullptr, cqkv,
        SQ, NC1, DM, DM, DM, NC1, 1.0f, nullptr);

    transpose_f16w<<<dim3(DM / 32, PR / 32), tb>>>(W_UQ, wuq,                        DM, PR);
    transpose_f16w<<<dim3(DM / 32, PR / 32), tb>>>(W_UV, wukuv + (size_t)PR * PR,    DM, PR);
    transpose_f16w<<<dim3(DM / 32, DM / 32), tb>>>(W_O,  wo,                         DM, DM);

    // knope|v = ckv @ [W_UK; W_UV]  (N=6144, fp16 out)
    gemm_f16<<<dim3(NKV / 128, SQ / 128), blk, GEMM_SMEM>>>(
        cqkv + PR, wukuv, nullptr, kvf,
        SQ, NKV, PR, NC1, PR, NKV, 1.0f, nullptr);

    // q = cq @ W_UQ  (fp16 out; rope applied inside FA)
    gemm_f16<<<dim3(DM / 128, SQ / 128), blk, GEMM_SMEM>>>(
        cqkv, wuq, nullptr, qf,
        SQ, DM, PR, NC1, PR, DM, 1.0f, nullptr);

    // krope rope (tiny, in place)
    rope_k16<<<(SQ * 32 + 255) / 256, blk>>>(cqkv, past);

    // fused attention -> fp16 [s][h*DH]  (K/V direct from producers; Q roped in-tile)
    fa_kernel<<<dim3(SQ / 64, NH), dim3(128), FA_SMEM>>>(qf, kvf, cqkv, aof, past);

    // out = attno @ W_O + b_O  (fp32)
    gemm_f16<<<dim3(DM / 128, SQ / 128), blk, GEMM_SMEM>>>(
        aof, wo, out, nullptr,
        SQ, DM, DM, DM, DM, DM, 1.0f, b_O);
}

// round 17
// speedup vs baseline: 1.0069x; 1.0069x over previous
#include <cuda_runtime.h>
#include <cuda_bf16.h>
#include <cuda_fp16.h>
#include <cstdint>
#include <math.h>

#define SQ   2048
#define DM   4096
#define PR   2048
#define NH   32
#define DH   128
#define RP   64
#define NKV  6144           // knope(2048) | v(4096)
#define NC1  4160           // cq(2048) | ckv(2048) | krope(64)

#define LOG2E  1.4426950408889634f

// ===================== small helpers ========================================
static __device__ __forceinline__ uint32_t smem_u32(const void* p) {
    uint32_t a;
    asm("{ .reg .u64 t; cvta.to.shared.u64 t, %1; cvt.u32.u64 %0, t; }"
        : "=r"(a) : "l"(p));
    return a;
}

// pack two floats -> fp16x2 (lo half = a, hi half = b)
static __device__ __forceinline__ uint32_t cvt_f16x2(float a, float b) {
    uint32_t r;
    asm("cvt.rn.f16x2.f32 %0, %1, %2;" : "=r"(r) : "f"(b), "f"(a));
    return r;
}

#define LDSM4(r, addr) \
    asm volatile("ldmatrix.sync.aligned.m8n8.x4.shared.b16 {%0,%1,%2,%3}, [%4];" \
        : "=r"((r)[0]), "=r"((r)[1]), "=r"((r)[2]), "=r"((r)[3]) : "r"(addr))

#define LDSM4_T(r, addr) \
    asm volatile("ldmatrix.sync.aligned.m8n8.x4.trans.shared.b16 {%0,%1,%2,%3}, [%4];" \
        : "=r"((r)[0]), "=r"((r)[1]), "=r"((r)[2]), "=r"((r)[3]) : "r"(addr))

#define MMA16(d, a, b0v, b1v) \
    asm volatile("mma.sync.aligned.m16n8k16.row.col.f32.f16.f16.f32 " \
        "{%0,%1,%2,%3}, {%4,%5,%6,%7}, {%8,%9}, {%0,%1,%2,%3};" \
        : "+f"((d)[0]), "+f"((d)[1]), "+f"((d)[2]), "+f"((d)[3]) \
        : "r"((a)[0]), "r"((a)[1]), "r"((a)[2]), "r"((a)[3]), "r"(b0v), "r"(b1v))

#define CP_ASYNC16(sp, gp) \
    asm volatile("cp.async.cg.shared.global [%0], [%1], 16;" :: "r"(sp), "l"(gp))
#define CP_COMMIT() asm volatile("cp.async.commit_group;" ::: "memory")
#define CP_WAIT3()  asm volatile("cp.async.wait_group 3;" ::: "memory")
#define CP_WAIT1()  asm volatile("cp.async.wait_group 1;" ::: "memory")

// ===================== scratch (device globals) =============================
__device__ __half g_xf  [(size_t)SQ * DM];
__device__ __half g_cqkv[(size_t)SQ * NC1];      // cq | ckv | krope
__device__ __half g_qf  [(size_t)SQ * DM];       // q (roped in place)
__device__ __half g_kvf [(size_t)SQ * NKV];      // knope | v
__device__ __half g_aof [(size_t)SQ * DM];

// fp16 weights ([N,K] K-major)
__device__ __half g_wdqkv[(size_t)NC1 * DM];     // [W_DQ; W_DKV; W_K_rope]
__device__ __half g_wuq  [(size_t)DM * PR];
__device__ __half g_wukuv[(size_t)NKV * PR];     // [W_UK; W_UV]
__device__ __half g_wo   [(size_t)DM * DM];

// ===================== single-fp16 HMMA GEMM ================================
// C = alpha * A @ B^T (+bias).  A: fp16 [M,K] row-major, B: fp16 [N,K] K-major.
// CTA tile 128x128, BK=32, 8 warps (2x4), warp tile 64x32, 4-stage cp.async.
#define STAGE_BYTES 20480
#define GEMM_SMEM   (4 * STAGE_BYTES)  // 81920

__global__ void __launch_bounds__(256, 2)
gemm_f16(const __half* __restrict__ Af, const __half* __restrict__ Bh,
         float* __restrict__ Cf, __half* __restrict__ Ch,
         int M, int N, int K, int lda, int ldb, int ldc,
         float alpha, const float* __restrict__ bias)
{
    extern __shared__ char smem[];
    const uint32_t sbase = smem_u32(smem);
    const int tid  = threadIdx.x;
    const int lane = tid & 31;
    const int w    = tid >> 5;
    const int wm   = w & 1;
    const int wn   = w >> 1;

    const int m0 = blockIdx.y * 128;
    const int n0 = blockIdx.x * 128;
    const int nk = K >> 5;

    const int lr   = tid >> 2;
    const int lcol = tid & 3;

    auto load_stage = [&](int kt, int slot) {
        const int k0 = kt << 5;
        const uint32_t sb = sbase + slot * STAGE_BYTES;
#pragma unroll
        for (int i = 0; i < 2; ++i) {
            const int r = lr + i * 64;
            const __half* gp = Af + (long long)(m0 + r) * lda + k0 + lcol * 8;
            CP_ASYNC16(sb + r * 80 + lcol * 16, gp);
        }
#pragma unroll
        for (int i = 0; i < 2; ++i) {
            const int r = lr + i * 64;
            int rn = n0 + r; if (rn >= N) rn = N - 1;
            const __half* gp = Bh + (long long)rn * ldb + k0 + lcol * 8;
            CP_ASYNC16(sb + 10240 + r * 80 + lcol * 16, gp);
        }
        CP_COMMIT();
    };

    const uint32_t aOff = (uint32_t)((wm * 64 + (lane & 15)) * 80 + ((lane >> 4) & 1) * 16);
    const uint32_t bOff = (uint32_t)((wn * 32 + ((lane >> 4) & 1) * 8 + (lane & 7)) * 80
                                     + ((lane >> 3) & 1) * 16);

    float acc[4][4][4];
#pragma unroll
    for (int a = 0; a < 4; a++)
#pragma unroll
        for (int b = 0; b < 4; b++)
#pragma unroll
            for (int c = 0; c < 4; c++) acc[a][b][c] = 0.0f;

    load_stage(0, 0);
    if (nk > 1) load_stage(1, 1); else CP_COMMIT();
    if (nk > 2) load_stage(2, 2); else CP_COMMIT();

    for (int kt = 0; kt < nk; ++kt) {
        if (kt + 3 < nk) load_stage(kt + 3, (kt + 3) & 3);
        else CP_COMMIT();
        CP_WAIT3();
        __syncthreads();

        const uint32_t sb = sbase + (kt & 3) * STAGE_BYTES;
#pragma unroll
        for (int kk = 0; kk < 2; ++kk) {
            uint32_t af[4][4], bh[2][4];
#pragma unroll
            for (int mt = 0; mt < 4; ++mt)
                LDSM4(af[mt], sb + aOff + mt * 1280 + kk * 32);
#pragma unroll
            for (int bt = 0; bt < 2; ++bt)
                LDSM4(bh[bt], sb + 10240 + bOff + bt * 1280 + kk * 32);
#pragma unroll
            for (int mt = 0; mt < 4; ++mt)
#pragma unroll
                for (int nt = 0; nt < 4; ++nt) {
                    const int bt = nt >> 1, s2 = (nt & 1) * 2;
                    MMA16(acc[mt][nt], af[mt], bh[bt][s2], bh[bt][s2 + 1]);
                }
        }
        __syncthreads();
    }

    const int er = lane >> 2;
    const int ec = (lane & 3) << 1;
#pragma unroll
    for (int mt = 0; mt < 4; ++mt) {
#pragma unroll
        for (int nt = 0; nt < 4; ++nt) {
            const int gr = m0 + wm * 64 + mt * 16 + er;
            const int gc = n0 + wn * 32 + nt * 8 + ec;
            if (gc >= N) continue;
            float v0 = acc[mt][nt][0] * alpha;
            float v1 = acc[mt][nt][1] * alpha;
            float v2 = acc[mt][nt][2] * alpha;
            float v3 = acc[mt][nt][3] * alpha;
            if (bias) {
                const float b0 = bias[gc], b1 = bias[gc + 1];
                v0 += b0; v1 += b1; v2 += b0; v3 += b1;
            }
            const long long o0 = (long long)gr * ldc + gc;
            const long long o1 = (long long)(gr + 8) * ldc + gc;
            if (Cf) {
                *(float2*)&Cf[o0] = make_float2(v0, v1);
                *(float2*)&Cf[o1] = make_float2(v2, v3);
            }
            if (Ch) {
                *(uint32_t*)&Ch[o0] = cvt_f16x2(v0, v1);
                *(uint32_t*)&Ch[o1] = cvt_f16x2(v2, v3);
            }
        }
    }
}

// ===================== fused flash attention =================================
// 64-row Q tiles, 128 threads (4 warps), 2 CTAs/SM.  Online softmax.
// Q: [s][h*DH+d].  K assembled on the fly: knope from kvf, krope from cqkv.
// V read directly from kvf rows (keys x d); PV uses ldmatrix.trans.
#define FA_QPITCH 272
#define FA_KPITCH 272
#define FA_VPITCH 272
#define FA_Q      0
#define FA_KBUF   17408                 // Q: 64*272
#define FA_VBUF   (FA_KBUF + 2 * 17408) // K: 2 bufs x 64*272
#define FA_SMEM   (FA_VBUF + 2 * 17408) // + V: 2 bufs x 64*272 = 87040

__global__ void __launch_bounds__(128, 2)
fa_kernel(const __half* __restrict__ Qf,
          const __half* __restrict__ kvf, const __half* __restrict__ cqkv,
          __half* __restrict__ O)
{
    extern __shared__ char smem[];
    const uint32_t sb = smem_u32(smem);
    const int tid  = threadIdx.x;
    const int lane = tid & 31;
    const int w    = tid >> 5;          // 0..3
    const int h    = blockIdx.y;
    const int m0   = blockIdx.x * 64;

    // Q tile: 64 rows x 256 B
    {
        const __half* qg = Qf + (size_t)m0 * DM + h * DH;
#pragma unroll
        for (int i = 0; i < 8; ++i) {
            const int id = tid + i * 128;
            const int r = id >> 4, c = id & 15;
            CP_ASYNC16(sb + FA_Q + r * FA_QPITCH + c * 16, qg + (size_t)r * DM + c * 8);
        }
    }
    auto loadKV = [&](int c, int buf) {
        const int k0 = c << 6;
        const uint32_t kb = sb + FA_KBUF + buf * 17408;
#pragma unroll
        for (int i = 0; i < 8; ++i) {
            const int id = tid + i * 128;
            const int r = id >> 4, cc = id & 15;
            const __half* gp;
            if (cc < 8)
                gp = kvf + (size_t)(k0 + r) * NKV + h * 64 + cc * 8;
            else
                gp = cqkv + (size_t)(k0 + r) * NC1 + 4096 + (cc - 8) * 8;
            CP_ASYNC16(kb + r * FA_KPITCH + cc * 16, gp);
        }
        const uint32_t vb = sb + FA_VBUF + buf * 17408;
#pragma unroll
        for (int i = 0; i < 8; ++i) {
            const int id = tid + i * 128;
            const int r = id >> 4, cc = id & 15;
            CP_ASYNC16(vb + r * FA_VPITCH + cc * 16,
                       kvf + (size_t)(k0 + r) * NKV + PR + h * DH + cc * 8);
        }
    };

    loadKV(0, 0);
    CP_COMMIT();

    const uint32_t qOff = sb + FA_Q + (w * 16 + (lane & 15)) * FA_QPITCH
                          + ((lane >> 4) & 1) * 16;
    const uint32_t kOff = (uint32_t)((((lane >> 4) & 1) * 8 + (lane & 7)) * FA_KPITCH
                          + ((lane >> 3) & 1) * 16);
    const uint32_t vOff = (uint32_t)(((lane & 7) + ((lane >> 3) & 1) * 8) * FA_VPITCH
                          + ((lane >> 4) & 1) * 16);

    float acc_o[16][4];
#pragma unroll
    for (int i = 0; i < 16; ++i)
#pragma unroll
        for (int j = 0; j < 4; ++j) acc_o[i][j] = 0.0f;

    float mr0 = -1e30f, mr1 = -1e30f, l0 = 0.0f, l1 = 0.0f;
    const float sc_al = 0.08838834764831845f * LOG2E;

    const int NC = SQ / 64;
    for (int c = 0; c < NC; ++c) {
        if (c + 1 < NC) loadKV(c + 1, (c + 1) & 1);
        CP_COMMIT();
        CP_WAIT1();
        __syncthreads();

        const uint32_t kb = sb + FA_KBUF + (c & 1) * 17408;
        const uint32_t vb = sb + FA_VBUF + (c & 1) * 17408;

        float s[8][4];
#pragma unroll
        for (int i = 0; i < 8; ++i)
#pragma unroll
            for (int j = 0; j < 4; ++j) s[i][j] = 0.0f;

#pragma unroll
        for (int kk = 0; kk < 8; ++kk) {
            uint32_t aq[4];
            LDSM4(aq, qOff + kk * 32);
#pragma unroll
            for (int ntp = 0; ntp < 4; ++ntp) {
                uint32_t kh4[4];
                LDSM4(kh4, kb + kOff + ntp * (16 * FA_KPITCH) + kk * 32);
                MMA16(s[2 * ntp],     aq, kh4[0], kh4[1]);
                MMA16(s[2 * ntp + 1], aq, kh4[2], kh4[3]);
            }
        }
#pragma unroll
        for (int nt = 0; nt < 8; ++nt)
#pragma unroll
            for (int j = 0; j < 4; ++j)
                s[nt][j] *= sc_al;

        float mx0 = -1e30f, mx1 = -1e30f;
#pragma unroll
        for (int nt = 0; nt < 8; ++nt) {
            mx0 = fmaxf(mx0, fmaxf(s[nt][0], s[nt][1]));
            mx1 = fmaxf(mx1, fmaxf(s[nt][2], s[nt][3]));
        }
        mx0 = fmaxf(mx0, __shfl_xor_sync(0xffffffffu, mx0, 1));
        mx0 = fmaxf(mx0, __shfl_xor_sync(0xffffffffu, mx0, 2));
        mx1 = fmaxf(mx1, __shfl_xor_sync(0xffffffffu, mx1, 1));
        mx1 = fmaxf(mx1, __shfl_xor_sync(0xffffffffu, mx1, 2));

        const float mn0 = fmaxf(mr0, mx0);
        const float mn1 = fmaxf(mr1, mx1);
        const float sc0 = exp2f(mr0 - mn0);
        const float sc1 = exp2f(mr1 - mn1);

        float rs0 = 0.0f, rs1 = 0.0f;
#pragma unroll
        for (int nt = 0; nt < 8; ++nt) {
            s[nt][0] = exp2f(s[nt][0] - mn0);
            s[nt][1] = exp2f(s[nt][1] - mn0);
            s[nt][2] = exp2f(s[nt][2] - mn1);
            s[nt][3] = exp2f(s[nt][3] - mn1);
            rs0 += s[nt][0] + s[nt][1];
            rs1 += s[nt][2] + s[nt][3];
        }
        rs0 += __shfl_xor_sync(0xffffffffu, rs0, 1);
        rs0 += __shfl_xor_sync(0xffffffffu, rs0, 2);
        rs1 += __shfl_xor_sync(0xffffffffu, rs1, 1);
        rs1 += __shfl_xor_sync(0xffffffffu, rs1, 2);

        l0 = l0 * sc0 + rs0;
        l1 = l1 * sc1 + rs1;
        mr0 = mn0;  mr1 = mn1;

#pragma unroll
        for (int nt = 0; nt < 16; ++nt) {
            acc_o[nt][0] *= sc0;  acc_o[nt][1] *= sc0;
            acc_o[nt][2] *= sc1;  acc_o[nt][3] *= sc1;
        }

#pragma unroll
        for (int kg = 0; kg < 4; ++kg) {
            uint32_t A[4];
            A[0] = cvt_f16x2(s[2 * kg][0],     s[2 * kg][1]);
            A[1] = cvt_f16x2(s[2 * kg][2],     s[2 * kg][3]);
            A[2] = cvt_f16x2(s[2 * kg + 1][0], s[2 * kg + 1][1]);
            A[3] = cvt_f16x2(s[2 * kg + 1][2], s[2 * kg + 1][3]);
#pragma unroll
            for (int dp = 0; dp < 8; ++dp) {
                uint32_t vh4[4];
                LDSM4_T(vh4, vb + vOff + kg * (16 * FA_VPITCH) + dp * 32);
                MMA16(acc_o[2 * dp],     A, vh4[0], vh4[1]);
                MMA16(acc_o[2 * dp + 1], A, vh4[2], vh4[3]);
            }
        }
        __syncthreads();
    }

    const float i0 = 1.0f / l0;
    const float i1 = 1.0f / l1;
    const int er = lane >> 2;
    const int ec = (lane & 3) << 1;
    const int gr0 = m0 + w * 16 + er;
    __half* ob = O + (size_t)gr0 * DM + h * DH + ec;
#pragma unroll
    for (int nt = 0; nt < 16; ++nt) {
        *(uint32_t*)(ob + nt * 8) =
            cvt_f16x2(acc_o[nt][0] * i0, acc_o[nt][1] * i0);
        *(uint32_t*)(ob + (size_t)8 * DM + nt * 8) =
            cvt_f16x2(acc_o[nt][2] * i1, acc_o[nt][3] * i1);
    }
}

// ===================== fp32 -> fp16 convert ==================================
__global__ void conv_f16(const float4* __restrict__ in, uint2* __restrict__ o, int n4)
{
    const int i = blockIdx.x * blockDim.x + threadIdx.x;
    if (i >= n4) return;
    const float4 f = in[i];
    o[i] = make_uint2(cvt_f16x2(f.x, f.y), cvt_f16x2(f.z, f.w));
}

// ===================== transpose fp32 [K,N] -> fp16 [N,K] ====================
__global__ void transpose_f16w(const float* __restrict__ in,
                               __half* __restrict__ o, int ldin, int ldout)
{
    __shared__ float t[32][33];
    const int c0 = blockIdx.x * 32, r0 = blockIdx.y * 32;
    const int tx = threadIdx.x, ty = threadIdx.y;
#pragma unroll
    for (int j = 0; j < 32; j += 8)
        t[ty + j][tx] = in[(long long)(r0 + ty + j) * ldin + c0 + tx];
    __syncthreads();
#pragma unroll
    for (int j = 0; j < 32; j += 8)
        o[(long long)(c0 + ty + j) * ldout + r0 + tx] = __float2half_rn(t[tx][ty + j]);
}

// ===================== RoPE (q + krope fused, in-place fp16) =================
__global__ void rope_all(__half* __restrict__ q, __half* __restrict__ cqkv,
                         const int* __restrict__ past)
{
    const int idx = blockIdx.x * blockDim.x + threadIdx.x;
    const int NQ = SQ * NH * 32;
    if (idx >= NQ + SQ * 32) return;

    int s, i;
    __half* base;
    if (idx < NQ) {
        s = idx / (NH * 32);
        const int r = idx % (NH * 32);
        i = r % 32;
        base = q + (size_t)s * DM + (r / 32) * DH + 64;
    } else {
        const int j = idx - NQ;
        s = j / 32;
        i = j % 32;
        base = cqkv + (size_t)s * NC1 + 4096;
    }

    const float fr = __expf(-(2.0f * (float)i / 128.0f) * 9.210340371976184f);
    const float ang = (float)(past[0] + s) * fr;
    const float c = cosf(ang), sn = sinf(ang);
    const float a = __half2float(base[i]);
    const float b = __half2float(base[i + 32]);
    base[i]      = __float2half_rn(a * c - b * sn);
    base[i + 32] = __float2half_rn(b * c + a * sn);
}

// ===================== launch ================================================
extern "C" void kernel_launch(void* const* d_in, const int* in_sizes, int n_in,
                              void* d_out, int out_size)
{
    const float* x        = (const float*)d_in[0];
    const float* W_DQ     = (const float*)d_in[1];
    const float* W_UQ     = (const float*)d_in[2];
    const float* W_DKV    = (const float*)d_in[3];
    const float* W_UK     = (const float*)d_in[4];
    const float* W_UV     = (const float*)d_in[5];
    const float* W_K_rope = (const float*)d_in[6];
    const float* W_O      = (const float*)d_in[7];
    const float* b_O      = (const float*)d_in[8];
    const int*   past     = (const int*)d_in[9];
    float* out = (float*)d_out;

    __half *xf, *cqkv, *qf, *kvf, *aof, *wdqkv, *wuq, *wukuv, *wo;
    cudaGetSymbolAddress((void**)&xf,    g_xf);
    cudaGetSymbolAddress((void**)&cqkv,  g_cqkv);
    cudaGetSymbolAddress((void**)&qf,    g_qf);
    cudaGetSymbolAddress((void**)&kvf,   g_kvf);
    cudaGetSymbolAddress((void**)&aof,   g_aof);
    cudaGetSymbolAddress((void**)&wdqkv, g_wdqkv);
    cudaGetSymbolAddress((void**)&wuq,   g_wuq);
    cudaGetSymbolAddress((void**)&wukuv, g_wukuv);
    cudaGetSymbolAddress((void**)&wo,    g_wo);

    cudaFuncSetAttribute(gemm_f16,  cudaFuncAttributeMaxDynamicSharedMemorySize, GEMM_SMEM);
    cudaFuncSetAttribute(fa_kernel, cudaFuncAttributeMaxDynamicSharedMemorySize, FA_SMEM);

    const dim3 blk(256);
    const dim3 tb(32, 8);

    // setup
    conv_f16<<<(SQ * DM / 4 + 255) / 256, blk>>>(
        (const float4*)x, (uint2*)xf, SQ * DM / 4);
    transpose_f16w<<<dim3(PR / 32, DM / 32), tb>>>(W_DQ,     wdqkv,                       PR, DM);
    transpose_f16w<<<dim3(PR / 32, DM / 32), tb>>>(W_DKV,    wdqkv + (size_t)PR * DM,     PR, DM);
    transpose_f16w<<<dim3(RP / 32, DM / 32), tb>>>(W_K_rope, wdqkv + (size_t)4096 * DM,   RP, DM);
    transpose_f16w<<<dim3(PR / 32, PR / 32), tb>>>(W_UK,     wukuv,                       PR, PR);

    // cq|ckv|krope = x @ [W_DQ; W_DKV; W_K_rope]  (N=4160, fp16 out)
    gemm_f16<<<dim3((NC1 + 127) / 128, SQ / 128), blk, GEMM_SMEM>>>(
        xf, wdqkv, nullptr, cqkv,
        SQ, NC1, DM, DM, DM, NC1, 1.0f, nullptr);

    transpose_f16w<<<dim3(DM / 32, PR / 32), tb>>>(W_UQ, wuq,                        DM, PR);
    transpose_f16w<<<dim3(DM / 32, PR / 32), tb>>>(W_UV, wukuv + (size_t)PR * PR,    DM, PR);
    transpose_f16w<<<dim3(DM / 32, DM / 32), tb>>>(W_O,  wo,                         DM, DM);

    // knope|v = ckv @ [W_UK; W_UV]  (N=6144, fp16 out)
    gemm_f16<<<dim3(NKV / 128, SQ / 128), blk, GEMM_SMEM>>>(
        cqkv + PR, wukuv, nullptr, kvf,
        SQ, NKV, PR, NC1, PR, NKV, 1.0f, nullptr);

    // q = cq @ W_UQ  (fp16 out, roped in place next)
    gemm_f16<<<dim3(DM / 128, SQ / 128), blk, GEMM_SMEM>>>(
        cqkv, wuq, nullptr, qf,
        SQ, DM, PR, NC1, PR, DM, 1.0f, nullptr);

    // RoPE (q + krope in one launch)
    rope_all<<<(SQ * NH * 32 + SQ * 32 + 255) / 256, blk>>>(qf, cqkv, past);

    // fused attention -> fp16 [s][h*DH]  (K and V read directly from producers)
    fa_kernel<<<dim3(SQ / 64, NH), dim3(128), FA_SMEM>>>(qf, kvf, cqkv, aof);

    // out = attno @ W_O + b_O  (fp32)
    gemm_f16<<<dim3(DM / 128, SQ / 128), blk, GEMM_SMEM>>>(
        aof, wo, out, nullptr,
        SQ, DM, DM, DM, DM, DM, 1.0f, b_O);
}